// round 1
// baseline (speedup 1.0000x reference)
#include <cuda_runtime.h>
#include <cstdint>

#define BN   2
#define NN   128
#define NP   (NN*NN)          // 16384
#define TOT  (BN*NP)          // 32768
#define KC   131
#define CC   21
#define WW   49
#define NCH  4                // k-chunks

// ---- scratch (static device globals; no runtime allocation) ----
__device__ float2 g_ew[(size_t)BN*KC*NP];          // (exp(xm), exp(-xm))  ~34MB
__device__ float  g_A[(size_t)NCH*WW*TOT];          // partial A per chunk  ~26MB
__device__ int    g_sel[TOT];
__device__ int    g_nsel;

// ---------------------------------------------------------------
// 0) compact selected pixels (single block, deterministic scan)
// ---------------------------------------------------------------
__global__ void compact_kernel(const int* __restrict__ mask) {
    __shared__ int sc[1024];
    int t = threadIdx.x;
    int base = t * 32;
    int cnt = 0;
    #pragma unroll
    for (int i = 0; i < 32; i++) cnt += (mask[base + i] != 0);
    sc[t] = cnt;
    __syncthreads();
    // inclusive Hillis-Steele scan over 1024
    for (int off = 1; off < 1024; off <<= 1) {
        int v = sc[t];
        int add = (t >= off) ? sc[t - off] : 0;
        __syncthreads();
        sc[t] = v + add;
        __syncthreads();
    }
    int j = sc[t] - cnt;   // exclusive offset
    #pragma unroll
    for (int i = 0; i < 32; i++) {
        int p = base + i;
        if (mask[p]) g_sel[j++] = p;
    }
    if (t == 1023) g_nsel = sc[1023];
}

// ---------------------------------------------------------------
// 1) EW precompute: xm = x * mask ; store (exp(xm), exp(-xm))
// ---------------------------------------------------------------
__global__ void ew_kernel(const float* __restrict__ integ,
                          const int*   __restrict__ mask) {
    int idx = blockIdx.x * 256 + threadIdx.x;       // < BN*KC*NP
    int b = idx / (KC * NP);
    int r = idx - b * KC * NP;
    int p = r % NP;
    int m = mask[b * NP + p];
    float x = m ? integ[idx] : 0.0f;
    g_ew[idx] = make_float2(__expf(x), __expf(-x));
}

// ---------------------------------------------------------------
// 2) stage 1: per selected pixel, per k-chunk, accumulate
//    A[w] += cp[k] * e_w / sum_w e_w    with e_w = max(Ep*Rq, Eq*Rp)
// ---------------------------------------------------------------
__global__ void __launch_bounds__(128, 4)
stage1_kernel(const float* __restrict__ cp) {
    __shared__ float scp[KC];
    for (int k = threadIdx.x; k < KC; k += 128) scp[k] = cp[k];
    __syncthreads();

    int i = blockIdx.x * 128 + threadIdx.x;
    if (i >= g_nsel) return;
    int gp = g_sel[i];
    int b  = gp >> 14;
    int p  = gp & (NP - 1);
    int py = p >> 7;
    int px = p & (NN - 1);

    int chunk = blockIdx.y;
    int k0 = (chunk * KC) / NCH;
    int k1 = ((chunk + 1) * KC) / NCH;

    const float2* __restrict__ ewb = g_ew + (size_t)b * KC * NP;

    float A[WW];
    #pragma unroll
    for (int w = 0; w < WW; w++) A[w] = 0.0f;

    for (int k = k0; k < k1; k++) {
        const float2* __restrict__ ewk = ewb + (size_t)k * NP;
        float2 ct = ewk[p];
        float e[WW];
        float esum = 0.0f;
        #pragma unroll
        for (int dy = -3; dy <= 3; dy++) {
            int ry = py + dy;
            bool rok = ((unsigned)ry < (unsigned)NN);
            #pragma unroll
            for (int dx = -3; dx <= 3; dx++) {
                int rx = px + dx;
                bool ok = rok && ((unsigned)rx < (unsigned)NN);
                float2 qv = ok ? ewk[ry * NN + rx] : make_float2(0.0f, 0.0f);
                float ev = fmaxf(ct.x * qv.y, qv.x * ct.y);
                int w = (dy + 3) * 7 + (dx + 3);
                e[w] = ev;
                esum += ev;
            }
        }
        float s = __fdividef(scp[k], esum);
        #pragma unroll
        for (int w = 0; w < WW; w++) A[w] = fmaf(s, e[w], A[w]);
    }

    size_t baseA = (size_t)chunk * WW * TOT + gp;
    #pragma unroll
    for (int w = 0; w < WW; w++) g_A[baseA + (size_t)w * TOT] = A[w];
}

// ---------------------------------------------------------------
// 3) stage 2: out[b,q,c] = sum_w A[p,w] * x2[b,c,p], p = q - off(w)
//    (gate by mask[p]; A of unselected pixels is never read)
// ---------------------------------------------------------------
__global__ void stage2_kernel(const float* __restrict__ x2,
                              const int*   __restrict__ mask,
                              float*       __restrict__ out) {
    int q = blockIdx.x * 256 + threadIdx.x;   // [0, TOT)
    int b  = q >> 14;
    int p  = q & (NP - 1);
    int qy = p >> 7;
    int qx = p & (NN - 1);
    const float* __restrict__ x2b = x2 + (size_t)b * CC * NP;

    float acc[CC];
    #pragma unroll
    for (int c = 0; c < CC; c++) acc[c] = 0.0f;

    #pragma unroll
    for (int oi = -3; oi <= 3; oi++) {
        int sy = qy - oi;
        bool rok = ((unsigned)sy < (unsigned)NN);
        #pragma unroll
        for (int oj = -3; oj <= 3; oj++) {
            int sx = qx - oj;
            bool ok = rok && ((unsigned)sx < (unsigned)NN);
            if (ok) {
                int pl = sy * NN + sx;
                int sp = b * NP + pl;
                if (mask[sp]) {
                    int w = (oi + 3) * 7 + (oj + 3);
                    size_t ai = (size_t)w * TOT + sp;
                    float a = g_A[ai]
                            + g_A[(size_t)1 * WW * TOT + ai]
                            + g_A[(size_t)2 * WW * TOT + ai]
                            + g_A[(size_t)3 * WW * TOT + ai];
                    #pragma unroll
                    for (int c = 0; c < CC; c++)
                        acc[c] = fmaf(a, x2b[(size_t)c * NP + pl], acc[c]);
                }
            }
        }
    }

    float* o = out + (size_t)q * CC;
    #pragma unroll
    for (int c = 0; c < CC; c++) o[c] = acc[c];
}

// ---------------------------------------------------------------
extern "C" void kernel_launch(void* const* d_in, const int* in_sizes, int n_in,
                              void* d_out, int out_size) {
    const float* integ = (const float*)d_in[0];   // [B,K,N,N]
    const float* x2    = (const float*)d_in[1];   // [B,C,N*N]
    const int*   msk   = (const int*)  d_in[2];   // [B,N,N]
    const float* cp    = (const float*)d_in[3];   // [K]
    float* out = (float*)d_out;                   // [B, N*N, C]

    compact_kernel<<<1, 1024>>>(msk);
    ew_kernel<<<(BN * KC * NP) / 256, 256>>>(integ, msk);

    dim3 g1((TOT + 127) / 128, NCH);
    stage1_kernel<<<g1, 128>>>(cp);

    stage2_kernel<<<TOT / 256, 256>>>(x2, msk, out);
}

// round 3
// speedup vs baseline: 1.5745x; 1.5745x over previous
#include <cuda_runtime.h>
#include <cuda_fp16.h>
#include <cstdint>

#define BN   2
#define NN   128
#define NP   (NN*NN)          // 16384
#define TOT  (BN*NP)          // 32768
#define KC   131
#define CC   21
#define WW   49
#define NCH  4                // k-chunks

// ---- scratch (static device globals; no runtime allocation) ----
__device__ __half2 g_ewh[(size_t)BN*KC*NP];        // (exp(xm), exp(-xm)) fp16  ~17MB
__device__ float   g_A[(size_t)NCH*WW*TOT];        // partial A per chunk  ~26MB
__device__ int     g_sel[TOT];
__device__ int     g_nsel;

// ---------------------------------------------------------------
// 0) compact selected pixels (single block, deterministic scan)
// ---------------------------------------------------------------
__global__ void compact_kernel(const int* __restrict__ mask) {
    __shared__ int sc[1024];
    int t = threadIdx.x;
    int base = t * 32;
    int cnt = 0;
    #pragma unroll
    for (int i = 0; i < 32; i++) cnt += (mask[base + i] != 0);
    sc[t] = cnt;
    __syncthreads();
    for (int off = 1; off < 1024; off <<= 1) {
        int v = sc[t];
        int add = (t >= off) ? sc[t - off] : 0;
        __syncthreads();
        sc[t] = v + add;
        __syncthreads();
    }
    int j = sc[t] - cnt;   // exclusive offset
    #pragma unroll
    for (int i = 0; i < 32; i++) {
        int p = base + i;
        if (mask[p]) g_sel[j++] = p;
    }
    if (t == 1023) g_nsel = sc[1023];
}

// ---------------------------------------------------------------
// 1) EW precompute: xm = x * mask ; store half2(exp(xm), exp(-xm))
// ---------------------------------------------------------------
__global__ void ew_kernel(const float* __restrict__ integ,
                          const int*   __restrict__ mask) {
    int idx = blockIdx.x * 256 + threadIdx.x;       // < BN*KC*NP
    int b = idx / (KC * NP);
    int p = idx & (NP - 1);
    int m = mask[b * NP + p];
    float x = m ? integ[idx] : 0.0f;
    g_ewh[idx] = __floats2half2_rn(__expf(x), __expf(-x));
}

// ---------------------------------------------------------------
// 2) stage 1: per selected pixel, per k-chunk:
//    A[w] += cp[k] * e_w / sum_w e_w   with  e_w = max(Ep*Rq, Eq*Rp)
//    (no spills: 2 CTAs/SM -> 256 regs/thread budget)
// ---------------------------------------------------------------
__global__ void __launch_bounds__(128, 2)
stage1_kernel(const float* __restrict__ cp) {
    __shared__ float scp[KC];
    for (int k = threadIdx.x; k < KC; k += 128) scp[k] = cp[k];
    __syncthreads();

    int i = blockIdx.x * 128 + threadIdx.x;
    if (i >= g_nsel) return;
    int gp = g_sel[i];
    int b  = gp >> 14;
    int p  = gp & (NP - 1);
    int py = p >> 7;
    int px = p & (NN - 1);

    int chunk = blockIdx.y;
    int k0 = (chunk * KC) / NCH;
    int k1 = ((chunk + 1) * KC) / NCH;

    const __half2* __restrict__ ewb = g_ewh + (size_t)b * KC * NP;

    float A[WW];
    #pragma unroll
    for (int w = 0; w < WW; w++) A[w] = 0.0f;

    for (int k = k0; k < k1; k++) {
        const __half2* __restrict__ ewk = ewb + (size_t)k * NP;
        float2 ct = __half22float2(ewk[p]);
        float e[WW];
        float esum = 0.0f;
        #pragma unroll
        for (int dy = -3; dy <= 3; dy++) {
            int ry = py + dy;
            bool rok = ((unsigned)ry < (unsigned)NN);
            const __half2* __restrict__ row = ewk + ry * NN;
            #pragma unroll
            for (int dx = -3; dx <= 3; dx++) {
                int rx = px + dx;
                bool ok = rok && ((unsigned)rx < (unsigned)NN);
                __half2 hv = __floats2half2_rn(0.0f, 0.0f);
                if (ok) hv = row[rx];
                float2 qv = __half22float2(hv);
                float ev = fmaxf(ct.x * qv.y, qv.x * ct.y);
                int w = (dy + 3) * 7 + (dx + 3);
                e[w] = ev;
                esum += ev;
            }
        }
        float s = __fdividef(scp[k], esum);
        #pragma unroll
        for (int w = 0; w < WW; w++) A[w] = fmaf(s, e[w], A[w]);
    }

    size_t baseA = (size_t)chunk * WW * TOT + gp;
    #pragma unroll
    for (int w = 0; w < WW; w++) g_A[baseA + (size_t)w * TOT] = A[w];
}

// ---------------------------------------------------------------
// 3) stage 2: out[b,q,c] = sum_w A[p,w] * x2[b,c,p], p = q - off(w)
//    Branch-free: clamped addresses, unconditional loads, SEL gating.
// ---------------------------------------------------------------
__global__ void __launch_bounds__(128)
stage2_kernel(const float* __restrict__ x2,
              const int*   __restrict__ mask,
              float*       __restrict__ out) {
    int q = blockIdx.x * 128 + threadIdx.x;   // [0, TOT)
    int b  = q >> 14;
    int p  = q & (NP - 1);
    int qy = p >> 7;
    int qx = p & (NN - 1);
    const float* __restrict__ x2b = x2 + (size_t)b * CC * NP;

    float acc[CC];
    #pragma unroll
    for (int c = 0; c < CC; c++) acc[c] = 0.0f;

    #pragma unroll
    for (int oi = -3; oi <= 3; oi++) {
        int sy = qy - oi;
        #pragma unroll
        for (int oj = -3; oj <= 3; oj++) {
            int sx = qx - oj;
            bool ok = ((unsigned)sy < (unsigned)NN) && ((unsigned)sx < (unsigned)NN);
            int pl = ok ? (sy * NN + sx) : p;       // clamp to a valid address
            int sp = b * NP + pl;
            int mv = mask[sp];
            int w = (oi + 3) * 7 + (oj + 3);
            size_t ai = (size_t)w * TOT + sp;
            float a0 = g_A[ai];
            float a1 = g_A[(size_t)1 * WW * TOT + ai];
            float a2 = g_A[(size_t)2 * WW * TOT + ai];
            float a3 = g_A[(size_t)3 * WW * TOT + ai];
            float a  = (ok && mv) ? ((a0 + a1) + (a2 + a3)) : 0.0f;
            #pragma unroll
            for (int c = 0; c < CC; c++)
                acc[c] = fmaf(a, x2b[(size_t)c * NP + pl], acc[c]);
        }
    }

    float* o = out + (size_t)q * CC;
    #pragma unroll
    for (int c = 0; c < CC; c++) o[c] = acc[c];
}

// ---------------------------------------------------------------
extern "C" void kernel_launch(void* const* d_in, const int* in_sizes, int n_in,
                              void* d_out, int out_size) {
    const float* integ = (const float*)d_in[0];   // [B,K,N,N]
    const float* x2    = (const float*)d_in[1];   // [B,C,N*N]
    const int*   msk   = (const int*)  d_in[2];   // [B,N,N]
    const float* cp    = (const float*)d_in[3];   // [K]
    float* out = (float*)d_out;                   // [B, N*N, C]

    compact_kernel<<<1, 1024>>>(msk);
    ew_kernel<<<(BN * KC * NP) / 256, 256>>>(integ, msk);

    dim3 g1((TOT + 127) / 128, NCH);
    stage1_kernel<<<g1, 128>>>(cp);

    stage2_kernel<<<TOT / 128, 128>>>(x2, msk, out);
}

// round 4
// speedup vs baseline: 1.8248x; 1.1590x over previous
#include <cuda_runtime.h>
#include <cuda_fp16.h>
#include <cstdint>

#define BN   2
#define NN   128
#define NP   (NN*NN)          // 16384
#define TOT  (BN*NP)          // 32768
#define KC   131
#define CC   21
#define WW   49
#define NCH  4                // k-chunks

// stage2 tiling
#define T2H  8
#define T2W  16
#define HH   (T2H + 6)        // 14
#define HW   (T2W + 6)        // 22
#define HPX  (HH * HW)        // 308
#define CPAD 24

// ---- scratch (static device globals; no runtime allocation) ----
__device__ __half2 g_ewh[(size_t)BN*KC*NP];        // (exp(xm), exp(-xm)) fp16  ~17MB
__device__ float   g_A[(size_t)NCH*WW*TOT];        // partial A per chunk  ~26MB
__device__ int     g_sel[TOT];
__device__ int     g_nsel;

// ---------------------------------------------------------------
// 0) compact selected pixels (single block, deterministic scan)
// ---------------------------------------------------------------
__global__ void compact_kernel(const int* __restrict__ mask) {
    __shared__ int sc[1024];
    int t = threadIdx.x;
    int base = t * 32;
    int cnt = 0;
    #pragma unroll
    for (int i = 0; i < 32; i++) cnt += (mask[base + i] != 0);
    sc[t] = cnt;
    __syncthreads();
    for (int off = 1; off < 1024; off <<= 1) {
        int v = sc[t];
        int add = (t >= off) ? sc[t - off] : 0;
        __syncthreads();
        sc[t] = v + add;
        __syncthreads();
    }
    int j = sc[t] - cnt;   // exclusive offset
    #pragma unroll
    for (int i = 0; i < 32; i++) {
        int p = base + i;
        if (mask[p]) g_sel[j++] = p;
    }
    if (t == 1023) g_nsel = sc[1023];
}

// ---------------------------------------------------------------
// 1) EW precompute: xm = x * mask ; store half2(exp(xm), exp(-xm))
// ---------------------------------------------------------------
__global__ void ew_kernel(const float* __restrict__ integ,
                          const int*   __restrict__ mask) {
    int idx = blockIdx.x * 256 + threadIdx.x;       // < BN*KC*NP
    int b = idx / (KC * NP);
    int p = idx & (NP - 1);
    int m = mask[b * NP + p];
    float x = m ? integ[idx] : 0.0f;
    g_ewh[idx] = __floats2half2_rn(__expf(x), __expf(-x));
}

// ---------------------------------------------------------------
// 2) stage 1: per selected pixel, per k-chunk:
//    A[w] += cp[k] * e_w / sum_w e_w ,  e_w = max(Ep*Rq, Eq*Rp)
//    e kept as 25 packed half2 pair-registers -> ~95 live regs,
//    4 CTAs/SM residency.
// ---------------------------------------------------------------
__device__ __forceinline__ __half2 ldnb(const __half2* __restrict__ ewk,
                                        int py, int px, int dy, int dx) {
    int ry = py + dy, rx = px + dx;
    bool ok = ((unsigned)ry < (unsigned)NN) && ((unsigned)rx < (unsigned)NN);
    __half2 v = __float2half2_rn(0.0f);
    if (ok) v = __ldg(ewk + ry * NN + rx);
    return v;
}

__global__ void __launch_bounds__(128, 4)
stage1_kernel(const float* __restrict__ cp) {
    __shared__ float scp[KC];
    for (int k = threadIdx.x; k < KC; k += 128) scp[k] = cp[k];
    __syncthreads();

    int i = blockIdx.x * 128 + threadIdx.x;
    if (i >= g_nsel) return;
    int gp = g_sel[i];
    int b  = gp >> 14;
    int p  = gp & (NP - 1);
    int py = p >> 7;
    int px = p & (NN - 1);

    int chunk = blockIdx.y;
    int k0 = (chunk * KC) / NCH;
    int k1 = ((chunk + 1) * KC) / NCH;

    const __half2* __restrict__ ewb = g_ewh + (size_t)b * KC * NP;

    float A[50];
    #pragma unroll
    for (int w = 0; w < 50; w++) A[w] = 0.0f;

    for (int k = k0; k < k1; k++) {
        const __half2* __restrict__ ewk = ewb + (size_t)k * NP;
        __half2 ct   = __ldg(ewk + p);
        __half2 ctEE = __low2half2(ct);    // (Ep,Ep)
        __half2 ctRR = __high2half2(ct);   // (Rp,Rp)

        __half2 eh[25];
        __half2 es2 = __float2half2_rn(0.0f);
        #pragma unroll
        for (int t = 0; t < 25; t++) {
            const int wa = 2 * t, wb = 2 * t + 1;
            __half2 qa = ldnb(ewk, py, px, wa / 7 - 3, wa % 7 - 3);
            __half2 qb = (wb < WW)
                       ? ldnb(ewk, py, px, wb / 7 - 3, wb % 7 - 3)
                       : __float2half2_rn(0.0f);
            __half2 EE = __lows2half2(qa, qb);   // (Ea,Eb)
            __half2 RR = __highs2half2(qa, qb);  // (Ra,Rb)
            __half2 e2 = __hmax2(__hmul2(ctEE, RR), __hmul2(EE, ctRR));
            eh[t] = e2;
            es2 = __hadd2(es2, e2);
        }
        float esum = __half2float(__hadd(__low2half(es2), __high2half(es2)));
        float s = __fdividef(scp[k], esum);
        #pragma unroll
        for (int t = 0; t < 25; t++) {
            float2 ef = __half22float2(eh[t]);
            A[2 * t]     = fmaf(s, ef.x, A[2 * t]);
            A[2 * t + 1] = fmaf(s, ef.y, A[2 * t + 1]);
        }
    }

    size_t baseA = (size_t)chunk * WW * TOT + gp;
    #pragma unroll
    for (int w = 0; w < WW; w++) g_A[baseA + (size_t)w * TOT] = A[w];
}

// ---------------------------------------------------------------
// 3) stage 2 (tiled): out[b,q,c] = sum_w A[p,w] * x2[b,c,p]
//    16x8 output tile / CTA; x2 halo staged in smem (mask-zeroed,
//    channel-padded to 24 for LDS.128); A partials read coalesced.
// ---------------------------------------------------------------
__global__ void __launch_bounds__(128)
stage2_kernel(const float* __restrict__ x2,
              const int*   __restrict__ mask,
              float*       __restrict__ out) {
    __shared__ float x2s[HPX * CPAD];   // ~29.6 KB
    __shared__ int   msks[HPX];

    int t  = threadIdx.x;
    int b  = blockIdx.z;
    int y0 = blockIdx.y * T2H;
    int x0 = blockIdx.x * T2W;
    const float* __restrict__ x2b = x2 + (size_t)b * CC * NP;

    // fill halo
    for (int idx = t; idx < HPX; idx += 128) {
        int hy = idx / HW, hx = idx - hy * HW;
        int gy = y0 + hy - 3, gx = x0 + hx - 3;
        bool ok = ((unsigned)gy < (unsigned)NN) && ((unsigned)gx < (unsigned)NN);
        int pl = ok ? (gy * NN + gx) : 0;
        int mv = ok ? mask[b * NP + pl] : 0;
        msks[idx] = mv;
        #pragma unroll
        for (int c = 0; c < CC; c++)
            x2s[idx * CPAD + c] = mv ? x2b[(size_t)c * NP + pl] : 0.0f;
        #pragma unroll
        for (int c = CC; c < CPAD; c++)
            x2s[idx * CPAD + c] = 0.0f;
    }
    __syncthreads();

    int tx = t & (T2W - 1);
    int ty = t >> 4;
    int qy = y0 + ty, qx = x0 + tx;
    int sp_base = b * NP;

    float acc[CPAD];
    #pragma unroll
    for (int c = 0; c < CPAD; c++) acc[c] = 0.0f;

    const float4* __restrict__ x2s4 = (const float4*)x2s;

    #pragma unroll
    for (int oi = -3; oi <= 3; oi++) {
        #pragma unroll
        for (int oj = -3; oj <= 3; oj++) {
            int hy = ty + 3 - oi;
            int hx = tx + 3 - oj;
            int h  = hy * HW + hx;
            int mv = msks[h];
            int gy = qy - oi, gx = qx - oj;
            int pl = mv ? (gy * NN + gx) : 0;    // mv=0 covers OOB too
            int w  = (oi + 3) * 7 + (oj + 3);
            size_t ai = (size_t)w * TOT + sp_base + pl;
            float a0 = g_A[ai];
            float a1 = g_A[(size_t)1 * WW * TOT + ai];
            float a2 = g_A[(size_t)2 * WW * TOT + ai];
            float a3 = g_A[(size_t)3 * WW * TOT + ai];
            float a  = mv ? ((a0 + a1) + (a2 + a3)) : 0.0f;
            #pragma unroll
            for (int j = 0; j < CPAD / 4; j++) {
                float4 xv = x2s4[h * (CPAD / 4) + j];
                acc[4 * j + 0] = fmaf(a, xv.x, acc[4 * j + 0]);
                acc[4 * j + 1] = fmaf(a, xv.y, acc[4 * j + 1]);
                acc[4 * j + 2] = fmaf(a, xv.z, acc[4 * j + 2]);
                acc[4 * j + 3] = fmaf(a, xv.w, acc[4 * j + 3]);
            }
        }
    }

    float* o = out + (size_t)(sp_base + qy * NN + qx) * CC;
    #pragma unroll
    for (int c = 0; c < CC; c++) o[c] = acc[c];
}

// ---------------------------------------------------------------
extern "C" void kernel_launch(void* const* d_in, const int* in_sizes, int n_in,
                              void* d_out, int out_size) {
    const float* integ = (const float*)d_in[0];   // [B,K,N,N]
    const float* x2    = (const float*)d_in[1];   // [B,C,N*N]
    const int*   msk   = (const int*)  d_in[2];   // [B,N,N]
    const float* cp    = (const float*)d_in[3];   // [K]
    float* out = (float*)d_out;                   // [B, N*N, C]

    compact_kernel<<<1, 1024>>>(msk);
    ew_kernel<<<(BN * KC * NP) / 256, 256>>>(integ, msk);

    dim3 g1((TOT + 127) / 128, NCH);
    stage1_kernel<<<g1, 128>>>(cp);

    dim3 g2(NN / T2W, NN / T2H, BN);
    stage2_kernel<<<g2, 128>>>(x2, msk, out);
}

// round 5
// speedup vs baseline: 2.3015x; 1.2612x over previous
#include <cuda_runtime.h>
#include <cuda_fp16.h>
#include <cstdint>

#define BN   2
#define NN   128
#define NP   (NN*NN)          // 16384
#define TOT  (BN*NP)          // 32768
#define KC   131
#define CC   21
#define WW   49
#define NCH  4                // k-chunks

// stage1 tile
#define S1W  16
#define S1H  8
#define S1HW 22
#define S1HH 14
#define S1PX (S1HW*S1HH)      // 308

// stage2 tile
#define T2W  16
#define T2H  8
#define HW2  22
#define HH2  14
#define HPX  (HW2*HH2)        // 308
#define CPAD 24

// ---- scratch (static device globals; no runtime allocation) ----
__device__ __half2 g_ewh[(size_t)BN*KC*NP];        // (exp(xm), exp(-xm)) fp16  ~17MB
__device__ float   g_A[(size_t)NCH*WW*TOT];        // partial A per chunk  ~26MB

// ---------------------------------------------------------------
// 1) EW precompute: xm = x * mask ; store half2(exp(xm), exp(-xm))
// ---------------------------------------------------------------
__global__ void ew_kernel(const float* __restrict__ integ,
                          const int*   __restrict__ mask) {
    int idx = blockIdx.x * 256 + threadIdx.x;       // < BN*KC*NP
    int b = idx / (KC * NP);
    int p = idx & (NP - 1);
    int m = mask[b * NP + p];
    float x = m ? integ[idx] : 0.0f;
    g_ewh[idx] = __floats2half2_rn(__expf(x), __expf(-x));
}

// ---------------------------------------------------------------
// 2) stage 1 (tiled): per pixel in a 16x8 tile, per k-chunk:
//    A[w] += cp[k] * e_w / sum_w e_w ,  e_w = max(Ep*Rq, Eq*Rp)
//    ew halo staged in smem, register-prefetched for k+1.
//    Computes ALL pixels; stage2 gates rows by mask.
// ---------------------------------------------------------------
__global__ void __launch_bounds__(128, 4)
stage1_kernel(const float* __restrict__ cp) {
    __shared__ __half2 sh[2][S1PX];
    __shared__ float   scp[KC];

    int t = threadIdx.x;
    for (int k = t; k < KC; k += 128) scp[k] = cp[k];

    int b     = blockIdx.z & 1;
    int chunk = blockIdx.z >> 1;
    int x0 = blockIdx.x * S1W;
    int y0 = blockIdx.y * S1H;
    int k0 = (chunk * KC) / NCH;
    int k1 = ((chunk + 1) * KC) / NCH;

    int tx = t & 15, ty = t >> 4;

    const __half2* __restrict__ ewb = g_ewh + (size_t)b * KC * NP;
    const __half2 zero = __float2half2_rn(0.0f);

    // precompute this thread's 3 halo fill slots (fixed across k)
    int off0, off1, off2;  bool ok0, ok1, ok2, has2;
    {
        int h0 = t, h1 = t + 128, h2 = t + 256;
        int hy0 = h0 / S1HW, hx0 = h0 - hy0 * S1HW;
        int hy1 = h1 / S1HW, hx1 = h1 - hy1 * S1HW;
        int hy2 = h2 / S1HW, hx2 = h2 - hy2 * S1HW;
        int gy0 = y0 + hy0 - 3, gx0 = x0 + hx0 - 3;
        int gy1 = y0 + hy1 - 3, gx1 = x0 + hx1 - 3;
        int gy2 = y0 + hy2 - 3, gx2 = x0 + hx2 - 3;
        ok0 = ((unsigned)gy0 < NN) && ((unsigned)gx0 < NN);
        ok1 = ((unsigned)gy1 < NN) && ((unsigned)gx1 < NN);
        has2 = (h2 < S1PX);
        ok2 = has2 && ((unsigned)gy2 < NN) && ((unsigned)gx2 < NN);
        off0 = gy0 * NN + gx0;
        off1 = gy1 * NN + gx1;
        off2 = ok2 ? (gy2 * NN + gx2) : 0;
        if (!ok0) off0 = 0;
        if (!ok1) off1 = 0;
    }

    float A[50];
    #pragma unroll
    for (int w = 0; w < 50; w++) A[w] = 0.0f;

    // prefetch k0
    __half2 r0, r1, r2;
    {
        const __half2* __restrict__ ewk = ewb + (size_t)k0 * NP;
        r0 = ok0 ? __ldg(ewk + off0) : zero;
        r1 = ok1 ? __ldg(ewk + off1) : zero;
        r2 = ok2 ? __ldg(ewk + off2) : zero;
    }

    for (int k = k0; k < k1; k++) {
        __half2* buf = sh[k & 1];
        buf[t]       = r0;
        buf[t + 128] = r1;
        if (has2) buf[t + 256] = r2;
        if (k + 1 < k1) {
            const __half2* __restrict__ ewn = ewb + (size_t)(k + 1) * NP;
            r0 = ok0 ? __ldg(ewn + off0) : zero;
            r1 = ok1 ? __ldg(ewn + off1) : zero;
            r2 = ok2 ? __ldg(ewn + off2) : zero;
        }
        __syncthreads();

        const __half2* __restrict__ c00 = buf + ty * S1HW + tx;
        __half2 ct   = c00[3 * S1HW + 3];
        __half2 ctEE = __low2half2(ct);    // (Ep,Ep)
        __half2 ctRR = __high2half2(ct);   // (Rp,Rp)

        __half2 eh[25];
        __half2 es2 = zero;
        #pragma unroll
        for (int pr = 0; pr < 24; pr++) {
            const int wa = 2 * pr, wb = wa + 1;
            __half2 qa = c00[(wa / 7) * S1HW + (wa % 7)];
            __half2 qb = c00[(wb / 7) * S1HW + (wb % 7)];
            __half2 EE = __lows2half2(qa, qb);
            __half2 RR = __highs2half2(qa, qb);
            __half2 e2 = __hmax2(__hmul2(ctEE, RR), __hmul2(EE, ctRR));
            eh[pr] = e2;
            es2 = __hadd2(es2, e2);
        }
        {   // singleton w=48 paired with zero
            __half2 qa = c00[6 * S1HW + 6];
            __half2 EE = __lows2half2(qa, zero);
            __half2 RR = __highs2half2(qa, zero);
            __half2 e2 = __hmax2(__hmul2(ctEE, RR), __hmul2(EE, ctRR));
            eh[24] = e2;
            es2 = __hadd2(es2, e2);
        }
        float esum = __half2float(__hadd(__low2half(es2), __high2half(es2)));
        float s = __fdividef(scp[k], esum);
        #pragma unroll
        for (int pr = 0; pr < 25; pr++) {
            float2 ef = __half22float2(eh[pr]);
            A[2 * pr]     = fmaf(s, ef.x, A[2 * pr]);
            A[2 * pr + 1] = fmaf(s, ef.y, A[2 * pr + 1]);
        }
    }

    int gp = b * NP + (y0 + ty) * NN + (x0 + tx);
    size_t baseA = (size_t)chunk * WW * TOT + gp;
    #pragma unroll
    for (int w = 0; w < WW; w++) g_A[baseA + (size_t)w * TOT] = A[w];
}

// ---------------------------------------------------------------
// 3) stage 2 (tiled + 4-way w-split): out[b,q,c] = sum_w A[p,w]*x2[b,c,p]
//    512 threads/CTA: warp lanes {0-7,8-15,16-23,24-31} handle
//    w-ranges {0-12,13-25,26-38,39-48} for 8 output pixels; combine
//    with two shfl_xor butterflies.
// ---------------------------------------------------------------
__global__ void __launch_bounds__(512)
stage2_kernel(const float* __restrict__ x2,
              const int*   __restrict__ mask,
              float*       __restrict__ out) {
    __shared__ float x2s[HPX * CPAD];   // ~29.6 KB
    __shared__ int   msks[HPX];

    int t  = threadIdx.x;
    int b  = blockIdx.z;
    int y0 = blockIdx.y * T2H;
    int x0 = blockIdx.x * T2W;
    const float* __restrict__ x2b = x2 + (size_t)b * CC * NP;

    // fill halo (308 px, one per thread)
    if (t < HPX) {
        int hy = t / HW2, hx = t - hy * HW2;
        int gy = y0 + hy - 3, gx = x0 + hx - 3;
        bool ok = ((unsigned)gy < NN) && ((unsigned)gx < NN);
        int pl = ok ? (gy * NN + gx) : 0;
        int mv = ok ? mask[b * NP + pl] : 0;
        msks[t] = mv;
        #pragma unroll
        for (int c = 0; c < CC; c++)
            x2s[t * CPAD + c] = mv ? x2b[(size_t)c * NP + pl] : 0.0f;
        #pragma unroll
        for (int c = CC; c < CPAD; c++)
            x2s[t * CPAD + c] = 0.0f;
    }
    __syncthreads();

    int lane = t & 31;
    int wid  = t >> 5;               // 0..15
    int wg   = lane >> 3;            // 0..3
    int q    = wid * 8 + (lane & 7); // 0..127
    int tx = q & 15, ty = q >> 4;
    int qy = y0 + ty, qx = x0 + tx;
    int spb = b * NP;

    float acc[CC];
    #pragma unroll
    for (int c = 0; c < CC; c++) acc[c] = 0.0f;

    int wbeg = wg * 13;
    int wend = (wbeg + 13 < WW) ? (wbeg + 13) : WW;

    for (int w = wbeg; w < wend; w++) {
        int di = (w * 37) >> 8;      // w/7 for w in [0,48]
        int dj = w - 7 * di;
        int hy = ty + 6 - di;
        int hx = tx + 6 - dj;
        int h  = hy * HW2 + hx;
        int mv = msks[h];
        int gy = qy + 3 - di, gx = qx + 3 - dj;
        int pl = mv ? (gy * NN + gx) : 0;
        size_t ai = (size_t)w * TOT + spb + pl;
        float a0 = g_A[ai];
        float a1 = g_A[(size_t)1 * WW * TOT + ai];
        float a2 = g_A[(size_t)2 * WW * TOT + ai];
        float a3 = g_A[(size_t)3 * WW * TOT + ai];
        float a  = mv ? ((a0 + a1) + (a2 + a3)) : 0.0f;
        const float4* __restrict__ xv4 = (const float4*)(x2s + h * CPAD);
        #pragma unroll
        for (int j = 0; j < 5; j++) {
            float4 xv = xv4[j];
            acc[4 * j + 0] = fmaf(a, xv.x, acc[4 * j + 0]);
            acc[4 * j + 1] = fmaf(a, xv.y, acc[4 * j + 1]);
            acc[4 * j + 2] = fmaf(a, xv.z, acc[4 * j + 2]);
            acc[4 * j + 3] = fmaf(a, xv.w, acc[4 * j + 3]);
        }
        acc[20] = fmaf(a, x2s[h * CPAD + 20], acc[20]);
    }

    // reduce the 4 w-groups (lanes xor 8 and xor 16)
    #pragma unroll
    for (int c = 0; c < CC; c++)
        acc[c] += __shfl_xor_sync(0xffffffffu, acc[c], 8);
    #pragma unroll
    for (int c = 0; c < CC; c++)
        acc[c] += __shfl_xor_sync(0xffffffffu, acc[c], 16);

    if (wg == 0) {
        float* o = out + (size_t)(spb + qy * NN + qx) * CC;
        #pragma unroll
        for (int c = 0; c < CC; c++) o[c] = acc[c];
    }
}

// ---------------------------------------------------------------
extern "C" void kernel_launch(void* const* d_in, const int* in_sizes, int n_in,
                              void* d_out, int out_size) {
    const float* integ = (const float*)d_in[0];   // [B,K,N,N]
    const float* x2    = (const float*)d_in[1];   // [B,C,N*N]
    const int*   msk   = (const int*)  d_in[2];   // [B,N,N]
    const float* cp    = (const float*)d_in[3];   // [K]
    float* out = (float*)d_out;                   // [B, N*N, C]

    ew_kernel<<<(BN * KC * NP) / 256, 256>>>(integ, msk);

    dim3 g1(NN / S1W, NN / S1H, BN * NCH);        // (8,16,8) = 1024 CTAs
    stage1_kernel<<<g1, 128>>>(cp);

    dim3 g2(NN / T2W, NN / T2H, BN);              // (8,16,2) = 256 CTAs
    stage2_kernel<<<g2, 512>>>(x2, msk, out);
}